// round 16
// baseline (speedup 1.0000x reference)
#include <cuda_runtime.h>
#include <cstdint>

#define CDIM    64
#define KCODES  1024
#define HWDIM   1024
#define BM      128
#define BN      64                  // codes per chunk
#define NCHUNK  (KCODES / BN)
#define NBLOCKS (65536 / BM)

// dynamic smem layout (float offsets)
#define SF_AH   0                                   // 8192: [ks][wid][lane*4] hi
#define SF_AL   8192                                // 8192: lo
#define SF_HN   16384                               // 1024
#define SF_C1   (SF_HN + KCODES)                    // 128 ints
#define SF_C2   (SF_C1 + 128)
#define SF_RS   (SF_C2 + 128)                       // 256 floats
#define SF_FIN  (SF_RS + 256)                       // 128 ints
#define SF_TOT  (SF_FIN + 128)
#define SMEM_BYTES (SF_TOT * 4)                     // 72192 B

__device__ float d_hn[KCODES];                      // 0.5*||c_k||^2
// per chunk: 8192 floats = [ks][row 0..3][128] hi, then 4096 lo (see prep)
__device__ float d_cb2[NCHUNK][8192];

// round-to-nearest fp32 -> tf32
static __forceinline__ __device__ uint32_t f2tf(float f) {
    uint32_t r;
    asm("cvt.rna.tf32.f32 %0, %1;" : "=r"(r) : "f"(f));
    return r;
}
// m16n8k8 tf32 MMA (baseline PTX, sm_80+)
static __forceinline__ __device__ void mma8(float* c, uint32_t a0, uint32_t a1,
                                            uint32_t a2, uint32_t a3,
                                            uint32_t b0, uint32_t b1) {
    asm("mma.sync.aligned.m16n8k8.row.col.f32.tf32.tf32.f32 "
        "{%0,%1,%2,%3}, {%4,%5,%6,%7}, {%8,%9}, {%0,%1,%2,%3};"
        : "+f"(c[0]), "+f"(c[1]), "+f"(c[2]), "+f"(c[3])
        : "r"(a0), "r"(a1), "r"(a2), "r"(a3), "r"(b0), "r"(b1));
}
static __forceinline__ __device__ bool lt(float v1, int i1, float v2, int i2) {
    return v1 < v2 || (v1 == v2 && i1 < i2);
}

// ---- prep: half-norms + split codebook in lane-contiguous fragment layout ----
__global__ void prep_kernel(const float* __restrict__ cb) {
    __shared__ float sc[64][65];                    // [code][k]
    const int ch = blockIdx.x;
    const int t  = threadIdx.x;
    #pragma unroll
    for (int i = 0; i < 4; ++i) {
        int e    = t + i * 256;                     // 1024 f4
        int code = e >> 4;
        int kf4  = e & 15;
        float4 v = __ldg(reinterpret_cast<const float4*>(cb + (ch * 64 + code) * CDIM + kf4 * 4));
        sc[code][kf4 * 4 + 0] = v.x;
        sc[code][kf4 * 4 + 1] = v.y;
        sc[code][kf4 * 4 + 2] = v.z;
        sc[code][kf4 * 4 + 3] = v.w;
    }
    __syncthreads();
    if (t < 64) {
        float s = 0.f;
        #pragma unroll
        for (int k = 0; k < 64; ++k) s += sc[t][k] * sc[t][k];
        d_hn[ch * 64 + t] = 0.5f * s;
    }
    #pragma unroll
    for (int i = 0; i < 16; ++i) {
        int o   = t + i * 256;                      // 0..4095, coalesced
        int ks  = o >> 9;
        int rr  = (o >> 7) & 3;
        int l   = (o >> 2) & 31;
        int m   = o & 3;
        int g   = l >> 2;
        int tig = l & 3;
        int code = ((rr >> 1) * 4 + m) * 8 + g;
        int k    = ks * 8 + tig + (rr & 1) * 4;
        float f = sc[code][k];
        uint32_t h = f2tf(f);
        d_cb2[ch][o]        = __uint_as_float(h);
        d_cb2[ch][4096 + o] = __uint_as_float(f2tf(f - __uint_as_float(h)));
    }
}

__global__ __launch_bounds__(256, 2) void vq_kernel(const float* __restrict__ x,
                                                    const float* __restrict__ cb,
                                                    float* __restrict__ out) {
    extern __shared__ float sm[];
    float* s_ah = sm + SF_AH;
    float* s_al = sm + SF_AL;
    float* s_hn = sm + SF_HN;
    int*   s_c1 = reinterpret_cast<int*>(sm + SF_C1);
    int*   s_c2 = reinterpret_cast<int*>(sm + SF_C2);
    float* s_rs = sm + SF_RS;
    int*   s_fin = reinterpret_cast<int*>(sm + SF_FIN);

    const int tid  = threadIdx.x;
    const int wid  = tid >> 5;
    const int lane = tid & 31;
    const int g    = lane >> 2;
    const int tig  = lane & 3;
    const int wrow = wid * 16;
    const int nbase = blockIdx.x * BM;
    const int b = nbase >> 10;
    const int p = nbase & 1023;
    const float* xin = x + b * (CDIM * HWDIM) + p;

    // ---- prologue: per-thread A-fragment split, once (chunk-invariant) ----
    {
        const int aoff0 = wid * 128 + lane * 4;
        #pragma unroll
        for (int ks = 0; ks < 8; ++ks) {
            int k0 = ks * 8 + tig;
            float af0 = __ldg(xin + k0 * HWDIM + wrow + g);
            float af1 = __ldg(xin + k0 * HWDIM + wrow + g + 8);
            float af2 = __ldg(xin + (k0 + 4) * HWDIM + wrow + g);
            float af3 = __ldg(xin + (k0 + 4) * HWDIM + wrow + g + 8);
            uint32_t h0 = f2tf(af0), h1 = f2tf(af1), h2 = f2tf(af2), h3 = f2tf(af3);
            float4 hv = make_float4(__uint_as_float(h0), __uint_as_float(h1),
                                    __uint_as_float(h2), __uint_as_float(h3));
            float4 lv = make_float4(
                __uint_as_float(f2tf(af0 - __uint_as_float(h0))),
                __uint_as_float(f2tf(af1 - __uint_as_float(h1))),
                __uint_as_float(f2tf(af2 - __uint_as_float(h2))),
                __uint_as_float(f2tf(af3 - __uint_as_float(h3))));
            *reinterpret_cast<float4*>(s_ah + ks * 1024 + aoff0) = hv;
            *reinterpret_cast<float4*>(s_al + ks * 1024 + aoff0) = lv;
        }
    }
    #pragma unroll
    for (int i = 0; i < 4; ++i) {
        int k = tid + i * 256;
        s_hn[k] = d_hn[k];
    }
    __syncthreads();                                // hn + A frags visible

    // top-2 running state (rows wrow+g, wrow+g+8)
    float bv0 = 3.4e38f, sv0 = 3.4e38f, bv1 = 3.4e38f, sv1 = 3.4e38f;
    int   bi0 = 0, si0 = 0, bi1 = 0, si1 = 0;

    const int aoff = wid * 128 + lane * 4;

    #pragma unroll 1
    for (int ch = 0; ch < NCHUNK; ++ch) {
        const float* bg = &d_cb2[ch][0] + lane * 4;
        // two half-passes: hc=0 -> slots 0-3 (B rows +0/+128), hc=1 -> slots 4-7 (+256/+384)
        #pragma unroll
        for (int hc = 0; hc < 2; ++hc) {
            const float* bgh = bg + hc * 256;
            float c[4][4];
            #pragma unroll
            for (int s = 0; s < 4; ++s)
                #pragma unroll
                for (int j = 0; j < 4; ++j) c[s][j] = 0.f;

            #pragma unroll
            for (int ks = 0; ks < 8; ++ks) {
                const float* bp = bgh + ks * 512;
                float4 hA = __ldg(reinterpret_cast<const float4*>(bp));          // b0
                float4 hB = __ldg(reinterpret_cast<const float4*>(bp + 128));    // b1
                float4 lA = __ldg(reinterpret_cast<const float4*>(bp + 4096));
                float4 lB = __ldg(reinterpret_cast<const float4*>(bp + 4224));
                float4 ah = *reinterpret_cast<const float4*>(s_ah + ks * 1024 + aoff);
                float4 al = *reinterpret_cast<const float4*>(s_al + ks * 1024 + aoff);
                uint32_t ah0 = __float_as_uint(ah.x), ah1 = __float_as_uint(ah.y);
                uint32_t ah2 = __float_as_uint(ah.z), ah3 = __float_as_uint(ah.w);
                uint32_t al0 = __float_as_uint(al.x), al1 = __float_as_uint(al.y);
                uint32_t al2 = __float_as_uint(al.z), al3 = __float_as_uint(al.w);

                #define FU(v) __float_as_uint(v)
                #define SLOT(S, H0, H1, L0, L1)                        \
                    mma8(c[S], ah0, ah1, ah2, ah3, FU(H0), FU(H1));    \
                    mma8(c[S], ah0, ah1, ah2, ah3, FU(L0), FU(L1));    \
                    mma8(c[S], al0, al1, al2, al3, FU(H0), FU(H1));
                SLOT(0, hA.x, hB.x, lA.x, lB.x)
                SLOT(1, hA.y, hB.y, lA.y, lB.y)
                SLOT(2, hA.z, hB.z, lA.z, lB.z)
                SLOT(3, hA.w, hB.w, lA.w, lB.w)
                #undef SLOT
                #undef FU
            }

            // ---- running top-2 (ascending col order; verified mapping) ----
            #pragma unroll
            for (int s = 0; s < 4; ++s) {
                int col0 = ch * BN + (hc * 4 + s) * 8 + 2 * tig;
                float hn0 = s_hn[col0];
                float hn1 = s_hn[col0 + 1];
                float s00 = hn0 - c[s][0];
                float s01 = hn1 - c[s][1];
                float s10 = hn0 - c[s][2];
                float s11 = hn1 - c[s][3];
                if (s00 < bv0) { sv0 = bv0; si0 = bi0; bv0 = s00; bi0 = col0; }
                else if (s00 < sv0) { sv0 = s00; si0 = col0; }
                if (s01 < bv0) { sv0 = bv0; si0 = bi0; bv0 = s01; bi0 = col0 + 1; }
                else if (s01 < sv0) { sv0 = s01; si0 = col0 + 1; }
                if (s10 < bv1) { sv1 = bv1; si1 = bi1; bv1 = s10; bi1 = col0; }
                else if (s10 < sv1) { sv1 = s10; si1 = col0; }
                if (s11 < bv1) { sv1 = bv1; si1 = bi1; bv1 = s11; bi1 = col0 + 1; }
                else if (s11 < sv1) { sv1 = s11; si1 = col0 + 1; }
            }
        }
    }

    // ---- merge top-2 across the 4 lanes of each group ----
    #pragma unroll
    for (int off = 2; off > 0; off >>= 1) {
        float oB0 = __shfl_down_sync(0xffffffffu, bv0, off, 4);
        int   oBi0 = __shfl_down_sync(0xffffffffu, bi0, off, 4);
        float oS0 = __shfl_down_sync(0xffffffffu, sv0, off, 4);
        int   oSi0 = __shfl_down_sync(0xffffffffu, si0, off, 4);
        float oB1 = __shfl_down_sync(0xffffffffu, bv1, off, 4);
        int   oBi1 = __shfl_down_sync(0xffffffffu, bi1, off, 4);
        float oS1 = __shfl_down_sync(0xffffffffu, sv1, off, 4);
        int   oSi1 = __shfl_down_sync(0xffffffffu, si1, off, 4);
        if (lt(oB0, oBi0, bv0, bi0)) {
            if (lt(bv0, bi0, oS0, oSi0)) { sv0 = bv0; si0 = bi0; }
            else                         { sv0 = oS0; si0 = oSi0; }
            bv0 = oB0; bi0 = oBi0;
        } else if (lt(oB0, oBi0, sv0, si0)) { sv0 = oB0; si0 = oBi0; }
        if (lt(oB1, oBi1, bv1, bi1)) {
            if (lt(bv1, bi1, oS1, oSi1)) { sv1 = bv1; si1 = bi1; }
            else                         { sv1 = oS1; si1 = oSi1; }
            bv1 = oB1; bi1 = oBi1;
        } else if (lt(oB1, oBi1, sv1, si1)) { sv1 = oB1; si1 = oBi1; }
    }
    if (tig == 0) {
        s_c1[wrow + g]     = bi0;  s_c2[wrow + g]     = si0;
        s_c1[wrow + g + 8] = bi1;  s_c2[wrow + g + 8] = si1;
    }
    __syncthreads();

    // ---- exact fp32 refinement of the two candidates per row (x from L2) ----
    {
        int row  = tid >> 1;
        int cand = tid & 1;
        int idx  = cand ? s_c2[row] : s_c1[row];
        const float4* cr = reinterpret_cast<const float4*>(cb + idx * CDIM);
        float dot = 0.f;
        #pragma unroll
        for (int i = 0; i < 16; ++i) {
            float4 v = __ldg(&cr[i]);
            const float* xr = xin + (i * 4) * HWDIM + row;
            dot = fmaf(__ldg(xr + 0 * HWDIM), v.x, dot);
            dot = fmaf(__ldg(xr + 1 * HWDIM), v.y, dot);
            dot = fmaf(__ldg(xr + 2 * HWDIM), v.z, dot);
            dot = fmaf(__ldg(xr + 3 * HWDIM), v.w, dot);
        }
        s_rs[row * 2 + cand] = s_hn[idx] - dot;
    }
    __syncthreads();
    if (tid < 128) {
        int   i1 = s_c1[tid], i2 = s_c2[tid];
        float v1 = s_rs[tid * 2], v2 = s_rs[tid * 2 + 1];
        s_fin[tid] = lt(v2, i2, v1, i1) ? i2 : i1;
    }
    __syncthreads();

    // ---- epilogue: gather winning code vectors, NCHW coalesced float4 ----
    float* outp = out + b * (CDIM * HWDIM) + p;
    #pragma unroll
    for (int i = 0; i < 8; ++i) {
        int e   = tid + i * 256;
        int chn = e >> 5;
        int r4  = e & 31;
        int i0 = s_fin[r4 * 4 + 0];
        int i1 = s_fin[r4 * 4 + 1];
        int i2 = s_fin[r4 * 4 + 2];
        int i3 = s_fin[r4 * 4 + 3];
        float4 o;
        o.x = __ldg(&cb[i0 * CDIM + chn]);
        o.y = __ldg(&cb[i1 * CDIM + chn]);
        o.z = __ldg(&cb[i2 * CDIM + chn]);
        o.w = __ldg(&cb[i3 * CDIM + chn]);
        *reinterpret_cast<float4*>(outp + chn * HWDIM + r4 * 4) = o;
    }
}

extern "C" void kernel_launch(void* const* d_in, const int* in_sizes, int n_in,
                              void* d_out, int out_size) {
    const float* x  = (const float*)d_in[0];   // inputs  [64,64,32,32]
    const float* cb = (const float*)d_in[1];   // codebook [1024,64]
    float* out = (float*)d_out;
    cudaFuncSetAttribute(vq_kernel, cudaFuncAttributeMaxDynamicSharedMemorySize, SMEM_BYTES);
    prep_kernel<<<NCHUNK, 256>>>(cb);
    vq_kernel<<<NBLOCKS, 256, SMEM_BYTES>>>(x, cb, out);
}

// round 17
// speedup vs baseline: 1.1218x; 1.1218x over previous
#include <cuda_runtime.h>
#include <cstdint>

#define CDIM    64
#define KCODES  1024
#define HWDIM   1024
#define BM      128
#define BN      64                  // codes per chunk
#define NCHUNK  (KCODES / BN)
#define NBLOCKS (65536 / BM)

// dynamic smem layout (float offsets)
#define SF_AH   0                                   // 8192: [ks][wid][lane*4] hi
#define SF_AL   8192                                // 8192: lo
#define SF_HN   16384                               // 1024
#define SF_C1   (SF_HN + KCODES)                    // 128 ints
#define SF_C2   (SF_C1 + 128)
#define SF_RS   (SF_C2 + 128)                       // 256 floats
#define SF_FIN  (SF_RS + 256)                       // 128 ints
#define SF_TOT  (SF_FIN + 128)
#define SMEM_BYTES (SF_TOT * 4)                     // 72192 B

__device__ float d_hn[KCODES];                      // 0.5*||c_k||^2
// per chunk: 8192 floats = [ks][row 0..3][128] hi, then 4096 lo (see prep)
__device__ float d_cb2[NCHUNK][8192];

// round-to-nearest fp32 -> tf32
static __forceinline__ __device__ uint32_t f2tf(float f) {
    uint32_t r;
    asm("cvt.rna.tf32.f32 %0, %1;" : "=r"(r) : "f"(f));
    return r;
}
// m16n8k8 tf32 MMA (baseline PTX, sm_80+)
static __forceinline__ __device__ void mma8(float* c, uint32_t a0, uint32_t a1,
                                            uint32_t a2, uint32_t a3,
                                            uint32_t b0, uint32_t b1) {
    asm("mma.sync.aligned.m16n8k8.row.col.f32.tf32.tf32.f32 "
        "{%0,%1,%2,%3}, {%4,%5,%6,%7}, {%8,%9}, {%0,%1,%2,%3};"
        : "+f"(c[0]), "+f"(c[1]), "+f"(c[2]), "+f"(c[3])
        : "r"(a0), "r"(a1), "r"(a2), "r"(a3), "r"(b0), "r"(b1));
}
static __forceinline__ __device__ bool lt(float v1, int i1, float v2, int i2) {
    return v1 < v2 || (v1 == v2 && i1 < i2);
}
// branchless single-best update: strict < keeps first occurrence (ascending cols)
#define UPD(bv, bi, sc, col) do {          \
    bool _p = (sc) < (bv);                 \
    (bv) = _p ? (sc) : (bv);               \
    (bi) = _p ? (col) : (bi);              \
} while (0)

// ---- prep: half-norms + split codebook in lane-contiguous fragment layout ----
__global__ void prep_kernel(const float* __restrict__ cb) {
    __shared__ float sc[64][65];                    // [code][k]
    const int ch = blockIdx.x;
    const int t  = threadIdx.x;
    #pragma unroll
    for (int i = 0; i < 4; ++i) {
        int e    = t + i * 256;                     // 1024 f4
        int code = e >> 4;
        int kf4  = e & 15;
        float4 v = __ldg(reinterpret_cast<const float4*>(cb + (ch * 64 + code) * CDIM + kf4 * 4));
        sc[code][kf4 * 4 + 0] = v.x;
        sc[code][kf4 * 4 + 1] = v.y;
        sc[code][kf4 * 4 + 2] = v.z;
        sc[code][kf4 * 4 + 3] = v.w;
    }
    __syncthreads();
    if (t < 64) {
        float s = 0.f;
        #pragma unroll
        for (int k = 0; k < 64; ++k) s += sc[t][k] * sc[t][k];
        d_hn[ch * 64 + t] = 0.5f * s;
    }
    #pragma unroll
    for (int i = 0; i < 16; ++i) {
        int o   = t + i * 256;                      // 0..4095, coalesced
        int ks  = o >> 9;
        int rr  = (o >> 7) & 3;
        int l   = (o >> 2) & 31;
        int m   = o & 3;
        int g   = l >> 2;
        int tig = l & 3;
        int code = ((rr >> 1) * 4 + m) * 8 + g;
        int k    = ks * 8 + tig + (rr & 1) * 4;
        float f = sc[code][k];
        uint32_t h = f2tf(f);
        d_cb2[ch][o]        = __uint_as_float(h);
        d_cb2[ch][4096 + o] = __uint_as_float(f2tf(f - __uint_as_float(h)));
    }
}

__global__ __launch_bounds__(256, 2) void vq_kernel(const float* __restrict__ x,
                                                    const float* __restrict__ cb,
                                                    float* __restrict__ out) {
    extern __shared__ float sm[];
    float* s_ah = sm + SF_AH;
    float* s_al = sm + SF_AL;
    float* s_hn = sm + SF_HN;
    int*   s_c1 = reinterpret_cast<int*>(sm + SF_C1);
    int*   s_c2 = reinterpret_cast<int*>(sm + SF_C2);
    float* s_rs = sm + SF_RS;
    int*   s_fin = reinterpret_cast<int*>(sm + SF_FIN);

    const int tid  = threadIdx.x;
    const int wid  = tid >> 5;
    const int lane = tid & 31;
    const int g    = lane >> 2;
    const int tig  = lane & 3;
    const int wrow = wid * 16;
    const int nbase = blockIdx.x * BM;
    const int b = nbase >> 10;
    const int p = nbase & 1023;
    const float* xin = x + b * (CDIM * HWDIM) + p;

    // ---- prologue: per-thread A-fragment split, once (chunk-invariant) ----
    {
        const int aoff0 = wid * 128 + lane * 4;
        #pragma unroll
        for (int ks = 0; ks < 8; ++ks) {
            int k0 = ks * 8 + tig;
            float af0 = __ldg(xin + k0 * HWDIM + wrow + g);
            float af1 = __ldg(xin + k0 * HWDIM + wrow + g + 8);
            float af2 = __ldg(xin + (k0 + 4) * HWDIM + wrow + g);
            float af3 = __ldg(xin + (k0 + 4) * HWDIM + wrow + g + 8);
            uint32_t h0 = f2tf(af0), h1 = f2tf(af1), h2 = f2tf(af2), h3 = f2tf(af3);
            float4 hv = make_float4(__uint_as_float(h0), __uint_as_float(h1),
                                    __uint_as_float(h2), __uint_as_float(h3));
            float4 lv = make_float4(
                __uint_as_float(f2tf(af0 - __uint_as_float(h0))),
                __uint_as_float(f2tf(af1 - __uint_as_float(h1))),
                __uint_as_float(f2tf(af2 - __uint_as_float(h2))),
                __uint_as_float(f2tf(af3 - __uint_as_float(h3))));
            *reinterpret_cast<float4*>(s_ah + ks * 1024 + aoff0) = hv;
            *reinterpret_cast<float4*>(s_al + ks * 1024 + aoff0) = lv;
        }
    }
    #pragma unroll
    for (int i = 0; i < 4; ++i) {
        int k = tid + i * 256;
        s_hn[k] = d_hn[k];
    }
    __syncthreads();                                // hn + A frags visible

    // two single-best trackers per row: A = slots 0-3, B = slots 4-7
    float bvA0 = 3.4e38f, bvB0 = 3.4e38f, bvA1 = 3.4e38f, bvB1 = 3.4e38f;
    int   biA0 = 0, biB0 = 32, biA1 = 0, biB1 = 32;

    const int aoff = wid * 128 + lane * 4;

    #pragma unroll 1
    for (int ch = 0; ch < NCHUNK; ++ch) {
        const float* bg = &d_cb2[ch][0] + lane * 4;
        float c[8][4];
        #pragma unroll
        for (int s = 0; s < 8; ++s)
            #pragma unroll
            for (int j = 0; j < 4; ++j) c[s][j] = 0.f;

        #pragma unroll
        for (int ks = 0; ks < 8; ++ks) {
            // B fragments: global, lane-contiguous, L1/L2-hot
            const float* bp = bg + ks * 512;
            float4 hA = __ldg(reinterpret_cast<const float4*>(bp));          // b0 slots 0-3
            float4 hB = __ldg(reinterpret_cast<const float4*>(bp + 128));    // b1 slots 0-3
            float4 hC = __ldg(reinterpret_cast<const float4*>(bp + 256));    // b0 slots 4-7
            float4 hD = __ldg(reinterpret_cast<const float4*>(bp + 384));    // b1 slots 4-7
            float4 lA = __ldg(reinterpret_cast<const float4*>(bp + 4096));
            float4 lB = __ldg(reinterpret_cast<const float4*>(bp + 4224));
            float4 lC = __ldg(reinterpret_cast<const float4*>(bp + 4352));
            float4 lD = __ldg(reinterpret_cast<const float4*>(bp + 4480));
            // A fragments: two LDS.128, conflict-free
            float4 ah = *reinterpret_cast<const float4*>(s_ah + ks * 1024 + aoff);
            float4 al = *reinterpret_cast<const float4*>(s_al + ks * 1024 + aoff);
            uint32_t ah0 = __float_as_uint(ah.x), ah1 = __float_as_uint(ah.y);
            uint32_t ah2 = __float_as_uint(ah.z), ah3 = __float_as_uint(ah.w);
            uint32_t al0 = __float_as_uint(al.x), al1 = __float_as_uint(al.y);
            uint32_t al2 = __float_as_uint(al.z), al3 = __float_as_uint(al.w);

            #define FU(v) __float_as_uint(v)
            #define SLOT(S, H0, H1, L0, L1)                        \
                mma8(c[S], ah0, ah1, ah2, ah3, FU(H0), FU(H1));    \
                mma8(c[S], ah0, ah1, ah2, ah3, FU(L0), FU(L1));    \
                mma8(c[S], al0, al1, al2, al3, FU(H0), FU(H1));
            SLOT(0, hA.x, hB.x, lA.x, lB.x)
            SLOT(1, hA.y, hB.y, lA.y, lB.y)
            SLOT(2, hA.z, hB.z, lA.z, lB.z)
            SLOT(3, hA.w, hB.w, lA.w, lB.w)
            SLOT(4, hC.x, hD.x, lC.x, lD.x)
            SLOT(5, hC.y, hD.y, lC.y, lD.y)
            SLOT(6, hC.z, hD.z, lC.z, lD.z)
            SLOT(7, hC.w, hD.w, lC.w, lD.w)
            #undef SLOT
            #undef FU
        }

        // ---- running single-best per half (ascending cols; strict < = first-min) ----
        #pragma unroll
        for (int s = 0; s < 8; ++s) {
            int col0 = ch * BN + s * 8 + 2 * tig;
            float hn0 = s_hn[col0];
            float hn1 = s_hn[col0 + 1];
            float s00 = hn0 - c[s][0];
            float s01 = hn1 - c[s][1];
            float s10 = hn0 - c[s][2];
            float s11 = hn1 - c[s][3];
            if (s < 4) {
                UPD(bvA0, biA0, s00, col0);
                UPD(bvA0, biA0, s01, col0 + 1);
                UPD(bvA1, biA1, s10, col0);
                UPD(bvA1, biA1, s11, col0 + 1);
            } else {
                UPD(bvB0, biB0, s00, col0);
                UPD(bvB0, biB0, s01, col0 + 1);
                UPD(bvB1, biB1, s10, col0);
                UPD(bvB1, biB1, s11, col0 + 1);
            }
        }
    }

    // ---- merge each tracker across the 4 lanes of the group (tie -> lower idx) ----
    #pragma unroll
    for (int off = 2; off > 0; off >>= 1) {
        float oA0 = __shfl_down_sync(0xffffffffu, bvA0, off, 4);
        int   oAi0 = __shfl_down_sync(0xffffffffu, biA0, off, 4);
        float oB0 = __shfl_down_sync(0xffffffffu, bvB0, off, 4);
        int   oBi0 = __shfl_down_sync(0xffffffffu, biB0, off, 4);
        float oA1 = __shfl_down_sync(0xffffffffu, bvA1, off, 4);
        int   oAi1 = __shfl_down_sync(0xffffffffu, biA1, off, 4);
        float oB1 = __shfl_down_sync(0xffffffffu, bvB1, off, 4);
        int   oBi1 = __shfl_down_sync(0xffffffffu, biB1, off, 4);
        if (lt(oA0, oAi0, bvA0, biA0)) { bvA0 = oA0; biA0 = oAi0; }
        if (lt(oB0, oBi0, bvB0, biB0)) { bvB0 = oB0; biB0 = oBi0; }
        if (lt(oA1, oAi1, bvA1, biA1)) { bvA1 = oA1; biA1 = oAi1; }
        if (lt(oB1, oBi1, bvB1, biB1)) { bvB1 = oB1; biB1 = oBi1; }
    }
    if (tig == 0) {
        s_c1[wrow + g]     = biA0;  s_c2[wrow + g]     = biB0;
        s_c1[wrow + g + 8] = biA1;  s_c2[wrow + g + 8] = biB1;
    }
    __syncthreads();

    // ---- exact fp32 refinement of the two candidates per row (x from L2) ----
    {
        int row  = tid >> 1;
        int cand = tid & 1;
        int idx  = cand ? s_c2[row] : s_c1[row];
        const float4* cr = reinterpret_cast<const float4*>(cb + idx * CDIM);
        float dot = 0.f;
        #pragma unroll
        for (int i = 0; i < 16; ++i) {
            float4 v = __ldg(&cr[i]);
            const float* xr = xin + (i * 4) * HWDIM + row;
            dot = fmaf(__ldg(xr + 0 * HWDIM), v.x, dot);
            dot = fmaf(__ldg(xr + 1 * HWDIM), v.y, dot);
            dot = fmaf(__ldg(xr + 2 * HWDIM), v.z, dot);
            dot = fmaf(__ldg(xr + 3 * HWDIM), v.w, dot);
        }
        s_rs[row * 2 + cand] = s_hn[idx] - dot;
    }
    __syncthreads();
    if (tid < 128) {
        int   i1 = s_c1[tid], i2 = s_c2[tid];
        float v1 = s_rs[tid * 2], v2 = s_rs[tid * 2 + 1];
        s_fin[tid] = lt(v2, i2, v1, i1) ? i2 : i1;
    }
    __syncthreads();

    // ---- epilogue: gather winning code vectors, NCHW coalesced float4 ----
    float* outp = out + b * (CDIM * HWDIM) + p;
    #pragma unroll
    for (int i = 0; i < 8; ++i) {
        int e   = tid + i * 256;
        int chn = e >> 5;
        int r4  = e & 31;
        int i0 = s_fin[r4 * 4 + 0];
        int i1 = s_fin[r4 * 4 + 1];
        int i2 = s_fin[r4 * 4 + 2];
        int i3 = s_fin[r4 * 4 + 3];
        float4 o;
        o.x = __ldg(&cb[i0 * CDIM + chn]);
        o.y = __ldg(&cb[i1 * CDIM + chn]);
        o.z = __ldg(&cb[i2 * CDIM + chn]);
        o.w = __ldg(&cb[i3 * CDIM + chn]);
        *reinterpret_cast<float4*>(outp + chn * HWDIM + r4 * 4) = o;
    }
}

extern "C" void kernel_launch(void* const* d_in, const int* in_sizes, int n_in,
                              void* d_out, int out_size) {
    const float* x  = (const float*)d_in[0];   // inputs  [64,64,32,32]
    const float* cb = (const float*)d_in[1];   // codebook [1024,64]
    float* out = (float*)d_out;
    cudaFuncSetAttribute(vq_kernel, cudaFuncAttributeMaxDynamicSharedMemorySize, SMEM_BYTES);
    prep_kernel<<<NCHUNK, 256>>>(cb);
    vq_kernel<<<NBLOCKS, 256, SMEM_BYTES>>>(x, cb, out);
}